// round 6
// baseline (speedup 1.0000x reference)
#include <cuda_runtime.h>
#include <cuda_bf16.h>
#include <cfloat>
#include <cstdint>

// ---------------------------------------------------------------------------
// RetinaNet postprocess, round 6: two kernels total.
//
//   prep    : grid kernel. Coalesced float4 class-max (SMEM atomicMax),
//             box decode+clip, direct slab emit for scores > CUTOFF.
//   postnms : ONE block. rank slab -> pairwise IoU masks in SMEM -> 1-warp
//             exact greedy -> (tail path: collect survivors vs kept snapshot,
//             serial reference greedy — skipped when 300 keeps found in slab)
//             -> per-keep class argmax -> output tuple. Resets g_scnt.
//
// Exactness: slab = {score > CUTOFF} is a clean cut in descending (score,idx)
// order; greedy over sort(slab) ++ tail is exact because the kept set is
// monotone and the tail path re-checks candidates in exact sorted order.
// Overflow (|slab| > T0, ~8-sigma event for this distribution) falls back to
// slab=empty => full serial greedy in tail path: slow but exact.
// ---------------------------------------------------------------------------

#define MAXA   262144
#define MAXDET 300
#define T0     1024
#define W0     16                 // 64-bit mask words per row
#define PSTTHD 0.05f
#define CUTOFF 0.99995f
#define NMSTHD 0.5f

typedef unsigned long long ull;

__device__ float  g_keys [MAXA];
__device__ float4 g_boxes[MAXA];
__device__ float  g_areas[MAXA];
__device__ ull    g_ckeys[T0];
__device__ ull    g_skey [MAXA];
__device__ int    g_scnt;

__device__ __forceinline__ bool sup_test(float x1, float y1, float x2, float y2, float ar,
                                         float X1, float Y1, float X2, float Y2, float AR)
{
    float xx1 = fmaxf(x1, X1);
    float yy1 = fmaxf(y1, Y1);
    float xx2 = fminf(x2, X2);
    float yy2 = fminf(y2, Y2);
    float inter = fmaxf(xx2 - xx1, 0.0f) * fmaxf(yy2 - yy1, 0.0f);
    float iou = inter / (ar + AR - inter + 1e-8f);
    return iou > NMSTHD;
}

// ---------------------------------------------------------------------------
// prep: 64 anchors per block of 256 threads. Class rows streamed as flat
// float4 (fully coalesced); per-row max via SMEM atomicMax (scores >= 0 so
// uint compare == float compare). Threads 0..63 then finalize: key write,
// slab emit, box decode.
// ---------------------------------------------------------------------------
__global__ void prep_kernel(const float* __restrict__ cls,
                            const float* __restrict__ reg,
                            const float* __restrict__ anc,
                            const int*   __restrict__ ph,
                            const int*   __restrict__ pw,
                            int A, int C)
{
    __shared__ unsigned srow[64];
    int t = threadIdx.x;
    int base = blockIdx.x * 64;
    if (t < 64) srow[t] = 0u;
    __syncthreads();

    if ((C & 3) == 0) {
        int f4r = C >> 2;                       // float4 per row (20 for C=80)
        int tot = 64 * f4r;
        const float4* cb = (const float4*)cls + (size_t)base * f4r;
        for (int i = t; i < tot; i += blockDim.x) {
            int r = i / f4r;
            if (base + r < A) {
                float4 v = cb[i];
                float m = fmaxf(fmaxf(v.x, v.y), fmaxf(v.z, v.w));
                atomicMax(&srow[r], __float_as_uint(m));
            }
        }
    } else {
        for (int i = t; i < 64 * C; i += blockDim.x) {
            int r = i / C;
            if (base + r < A) {
                float m = cls[(size_t)(base + r) * C + (i % C)];
                atomicMax(&srow[r], __float_as_uint(m));
            }
        }
    }
    __syncthreads();

    if (t < 64) {
        int a = base + t;
        if (a < A) {
            float m = __uint_as_float(srow[t]);
            g_keys[a] = (m > PSTTHD) ? m : 0.0f;
            if (m > CUTOFF) {
                int p = atomicAdd(&g_scnt, 1);
                if (p < T0)
                    g_ckeys[p] = ((ull)__float_as_uint(m) << 18) |
                                 (ull)(0x3FFFFu - (unsigned)a);
            }

            float4 an = ((const float4*)anc)[a];
            float4 rg = ((const float4*)reg)[a];
            float bw = an.z - an.x;
            float bh = an.w - an.y;
            float cx = an.x + 0.5f * bw;
            float cy = an.y + 0.5f * bh;
            float pcx = cx + (rg.x * 0.1f) * bw;
            float pcy = cy + (rg.y * 0.1f) * bh;
            float pw_ = expf(rg.z * 0.2f) * bw;
            float ph_ = expf(rg.w * 0.2f) * bh;

            float W = pw ? (float)__ldg(pw) : 1024.0f;
            float H = ph ? (float)__ldg(ph) : 1024.0f;

            float x1 = fmaxf(pcx - 0.5f * pw_, 0.0f);
            float y1 = fmaxf(pcy - 0.5f * ph_, 0.0f);
            float x2 = fminf(pcx + 0.5f * pw_, W);
            float y2 = fminf(pcy + 0.5f * ph_, H);

            g_boxes[a] = make_float4(x1, y1, x2, y2);
            g_areas[a] = (x2 - x1) * (y2 - y1);
        }
    }
}

// ---------------------------------------------------------------------------
// postnms: one block, 1024 threads. Everything after prep.
// ---------------------------------------------------------------------------
__global__ void __launch_bounds__(1024, 1)
postnms_kernel(const float* __restrict__ cls, int A, int C,
               float* __restrict__ out)
{
    extern __shared__ ull smasks[];            // T0*W0 = 128 KB dynamic
    __shared__ ull    skeys[T0];               // reused as tail reduction buf
    __shared__ int    sidx [T0];
    __shared__ float4 scb  [T0];
    __shared__ float  sca  [T0];
    __shared__ float4 skb  [MAXDET];
    __shared__ float  skar [MAXDET];
    __shared__ int    skeep[MAXDET];
    __shared__ int    spos [MAXDET];
    __shared__ int    s_nk, s_ns;
    __shared__ float4 swin;
    __shared__ float  swar;

    int t = threadIdx.x;
    int scnt = g_scnt;
    bool overflow = scnt > T0;
    int n = overflow ? 0 : scnt;

    // ---- rank by comparison (keys unique) + gather into sorted order ----
    skeys[t] = (t < n) ? g_ckeys[t] : 0ULL;
    __syncthreads();
    if (t < n) {
        ull mykey = skeys[t];
        int r = 0;
        for (int j = 0; j < n; j++) r += (skeys[j] > mykey) ? 1 : 0;
        int a = (int)(0x3FFFFu - (unsigned)(mykey & 0x3FFFFULL));
        sidx[r] = a;
        scb[r]  = g_boxes[a];
        sca[r]  = g_areas[a];
    }
    if (t == 0) { s_nk = 0; s_ns = 0; }
    __syncthreads();

    // ---- pairwise suppression masks into SMEM ----
    int items = n * W0;
    for (int it = t; it < items; it += 1024) {
        int i = it >> 4;
        int w = it & 15;
        int jbase = w << 6;
        ull word = 0ULL;
        if (jbase < i) {
            float4 bi = scb[i];
            float  ai = sca[i];
            int jend = min(jbase + 64, i);
            for (int j = jbase; j < jend; j++) {
                float4 bj = scb[j];
                if (sup_test(bi.x, bi.y, bi.z, bi.w, ai,
                             bj.x, bj.y, bj.z, bj.w, sca[j]))
                    word |= 1ULL << (j - jbase);
            }
        }
        smasks[it] = word;
    }
    __syncthreads();

    // ---- 1-warp exact greedy over slab (prefetched rows) ----
    if (t < 32) {
        int lane = t;
        ull kept = 0ULL;
        int nk = 0;
        ull nrow = (n > 0 && lane < W0) ? smasks[lane] : 0ULL;
        for (int i = 0; i < n; i++) {
            ull row = nrow;
            nrow = (i + 1 < n && lane < W0) ? smasks[(i + 1) * W0 + lane] : 0ULL;
            bool hit = (row & kept) != 0ULL;
            if (!__any_sync(0xffffffffu, hit)) {
                if (lane == (i >> 6)) kept |= 1ULL << (i & 63);
                if (lane == 0) spos[nk] = i;
                nk++;
                if (nk >= MAXDET) break;
            }
        }
        if (lane == 0) s_nk = nk;
    }
    __syncthreads();
    int nk = s_nk;
    for (int k = t; k < nk; k += 1024) {
        int p = spos[k];
        skb[k]   = scb[p];
        skar[k]  = sca[p];
        skeep[k] = sidx[p];
    }
    __syncthreads();

    // ---- tail path (skipped when slab already yielded 300 keeps) ----
    if (nk < MAXDET) {
        for (int a = t; a < A; a += 1024) {
            float k = g_keys[a];
            if (!(k > PSTTHD)) continue;
            if (!overflow && k > CUTOFF) continue;      // slab member
            float4 b = g_boxes[a];
            float ar = g_areas[a];
            bool sup = false;
            for (int kk = 0; kk < nk; kk++) {
                if (sup_test(b.x, b.y, b.z, b.w, ar,
                             skb[kk].x, skb[kk].y, skb[kk].z, skb[kk].w, skar[kk])) {
                    sup = true;
                    break;
                }
            }
            if (!sup) {
                int p = atomicAdd(&s_ns, 1);
                g_skey[p] = ((ull)__float_as_uint(k) << 18) |
                            (ull)(0x3FFFFu - (unsigned)a);
            }
        }
        __syncthreads();
        int ns = s_ns;
        ull* sb = skeys;                                // reuse storage
        while (nk < MAXDET && ns > 0) {
            ull best = 0ULL;
            for (int i = t; i < ns; i += 1024) {
                ull v = g_skey[i];
                if (v > best) best = v;
            }
            sb[t] = best;
            __syncthreads();
            for (int off = 512; off; off >>= 1) {
                if (t < off && sb[t + off] > sb[t]) sb[t] = sb[t + off];
                __syncthreads();
            }
            if (sb[0] == 0ULL) break;

            if (t == 0) {
                int a = (int)(0x3FFFFu - (unsigned)(sb[0] & 0x3FFFFULL));
                float4 b = g_boxes[a];
                float ar = g_areas[a];
                skeep[nk] = a;
                skb[nk]   = b;
                skar[nk]  = ar;
                swin = b;
                swar = ar;
            }
            __syncthreads();
            float4 wb = swin;
            float war = swar;
            for (int i = t; i < ns; i += 1024) {
                ull v = g_skey[i];
                if (v != 0ULL) {
                    int a = (int)(0x3FFFFu - (unsigned)(v & 0x3FFFFULL));
                    float4 b = g_boxes[a];
                    if (sup_test(b.x, b.y, b.z, b.w, g_areas[a],
                                 wb.x, wb.y, wb.z, wb.w, war))
                        g_skey[i] = 0ULL;               // winner self-suppresses too
                }
            }
            nk++;
            __syncthreads();
        }
    }
    __syncthreads();

    // ---- final: warp per keep, class argmax (first-max), output tuple ----
    int warp = t >> 5;
    int lane = t & 31;
    for (int d = warp; d < MAXDET; d += 32) {
        bool valid = d < nk;
        float score = 0.f, clsid = -1.f;
        float bx0 = 0.f, bx1 = 0.f, bx2 = 0.f, bx3 = 0.f;
        if (valid) {
            int idx = skeep[d];
            const float* row = cls + (size_t)idx * C;
            float best = -FLT_MAX;
            int bi = 0x7fffffff;
            for (int c = lane; c < C; c += 32) {
                float vv = row[c];
                if (vv > best) { best = vv; bi = c; }
            }
            #pragma unroll
            for (int off = 16; off; off >>= 1) {
                float ov = __shfl_down_sync(0xffffffffu, best, off);
                int   oi = __shfl_down_sync(0xffffffffu, bi,   off);
                if (ov > best || (ov == best && oi < bi)) { best = ov; bi = oi; }
            }
            best = __shfl_sync(0xffffffffu, best, 0);
            bi   = __shfl_sync(0xffffffffu, bi,   0);
            score = best;
            clsid = (float)bi;
            float4 b = skb[d];
            bx0 = b.x; bx1 = b.y; bx2 = b.z; bx3 = b.w;
        }
        if (lane == 0) {
            out[d]                      = score;
            out[MAXDET + d]             = clsid;
            out[2 * MAXDET + 4 * d + 0] = bx0;
            out[2 * MAXDET + 4 * d + 1] = bx1;
            out[2 * MAXDET + 4 * d + 2] = bx2;
            out[2 * MAXDET + 4 * d + 3] = bx3;
            out[6 * MAXDET + d]         = valid ? 1.0f : 0.0f;
        }
    }

    // ---- reset persistent counter for next graph replay ----
    if (t == 0) g_scnt = 0;
}

// ---------------------------------------------------------------------------
extern "C" void kernel_launch(void* const* d_in, const int* in_sizes, int n_in,
                              void* d_out, int out_size)
{
    const float* cls = (const float*)d_in[0];
    const float* reg = (const float*)d_in[1];
    const float* anc = (const float*)d_in[2];
    const int*   ph  = (n_in > 3) ? (const int*)d_in[3] : nullptr;
    const int*   pw  = (n_in > 4) ? (const int*)d_in[4] : nullptr;

    int A = in_sizes[2] / 4;
    if (A > MAXA) A = MAXA;
    int C = in_sizes[0] / A;

    cudaFuncSetAttribute(postnms_kernel,
                         cudaFuncAttributeMaxDynamicSharedMemorySize,
                         T0 * W0 * (int)sizeof(ull));

    prep_kernel<<<(A + 63) / 64, 256>>>(cls, reg, anc, ph, pw, A, C);
    postnms_kernel<<<1, 1024, T0 * W0 * sizeof(ull)>>>(cls, A, C, (float*)d_out);
}